// round 13
// baseline (speedup 1.0000x reference)
#include <cuda_runtime.h>
#include <cuda_fp16.h>
#include <math.h>
#include <stdint.h>

// Problem dims
#define BATCH 4096
#define HID   1024
#define INF   2048           // input + hidden
#define GATES 4096           // 4*HID

// GEMM tiling (fp16 single product)
#define BM 128
#define BN 256
#define KC 64                // K fp16 elems per stage (128B rows, SW128)
#define NSTAGE 4
#define NKIT (INF / KC)      // 32
#define NTHREADS 512

#define A_TILE_BYTES (BM * 128)              // 16KB
#define B_TILE_BYTES (BN * 128)              // 32KB
#define STAGE_BYTES  (A_TILE_BYTES + B_TILE_BYTES)   // 48KB
#define SMEM_TOTAL   (NSTAGE * STAGE_BYTES)  // 196608

static __device__ __forceinline__ uint32_t sw128(uint32_t o) {
    return o ^ ((o >> 3) & 0x70);
}
static __device__ __forceinline__ uint32_t smem_u32(const void* p) {
    uint32_t a;
    asm("{ .reg .u64 t; cvta.to.shared.u64 t, %1; cvt.u32.u64 %0, t; }" : "=r"(a) : "l"(p));
    return a;
}

#define CP_ASYNC16(dst, src) \
    asm volatile("cp.async.cg.shared.global [%0], [%1], 16;" :: "r"(dst), "l"(src))
#define CP_COMMIT() asm volatile("cp.async.commit_group;" ::: "memory")
#define CP_WAIT2()  asm volatile("cp.async.wait_group 2;" ::: "memory")
#define CP_WAIT1()  asm volatile("cp.async.wait_group 1;" ::: "memory")
#define CP_WAIT0()  asm volatile("cp.async.wait_group 0;" ::: "memory")

#define LDMX4(r0, r1, r2, r3, a) \
    asm volatile("ldmatrix.sync.aligned.m8n8.x4.shared.b16 {%0,%1,%2,%3}, [%4];" \
                 : "=r"(r0), "=r"(r1), "=r"(r2), "=r"(r3) : "r"(a))

#define MMA_F16(d, a, b0, b1) \
    asm volatile("mma.sync.aligned.m16n8k16.row.col.f32.f16.f16.f32 " \
                 "{%0,%1,%2,%3}, {%4,%5,%6,%7}, {%8,%9}, {%0,%1,%2,%3};" \
                 : "+f"(d[0]), "+f"(d[1]), "+f"(d[2]), "+f"(d[3]) \
                 : "r"(a[0]), "r"(a[1]), "r"(a[2]), "r"(a[3]), "r"(b0), "r"(b1))

// ---------------- device scratch ----------------
__device__ __half g_x1[(size_t)BATCH * INF];   // fp16(concat(input,hx))
__device__ __half g_w1[(size_t)GATES * INF];   // fp16(W), row j = 4h+gate

// ---------------- merged pack kernel ----------------
#define XUNITS ((BATCH * INF) / 4)             // 2097152
#define WUNITS ((GATES * INF) / 4)             // 2097152

__global__ void pack_all_kernel(const float* __restrict__ inp,
                                const float* __restrict__ hx,
                                const float* __restrict__ Wi,
                                const float* __restrict__ Wf,
                                const float* __restrict__ Wg,
                                const float* __restrict__ Wo) {
    int idx = blockIdx.x * blockDim.x + threadIdx.x;
    if (idx < XUNITS) {
        int elem = idx * 4;
        int b = elem >> 11;
        int k = elem & 2047;
        float4 v;
        if (k < HID) v = *(const float4*)(inp + (size_t)b * HID + k);
        else         v = *(const float4*)(hx  + (size_t)b * HID + (k - HID));
        __half q[4];
        q[0] = __float2half_rn(v.x);
        q[1] = __float2half_rn(v.y);
        q[2] = __float2half_rn(v.z);
        q[3] = __float2half_rn(v.w);
        *(uint64_t*)(g_x1 + elem) = *(uint64_t*)q;
    } else {
        long elem = (long)(idx - XUNITS) * 4;
        if (elem >= (long)GATES * INF) return;
        int j = (int)(elem >> 11);      // dest row = 4h+gate
        int k = (int)(elem & 2047);
        int gate = j & 3;
        int h    = j >> 2;
        const float* W = (gate == 0) ? Wi : (gate == 1) ? Wf : (gate == 2) ? Wg : Wo;
        float4 v = *(const float4*)(W + (long)h * INF + k);
        __half q[4];
        q[0] = __float2half_rn(v.x);
        q[1] = __float2half_rn(v.y);
        q[2] = __float2half_rn(v.z);
        q[3] = __float2half_rn(v.w);
        *(uint64_t*)(g_w1 + elem) = *(uint64_t*)q;
    }
}

// ---------------- stage loader (cp.async, SW128 swizzled) ----------------
__device__ __forceinline__ void load_stage(uint32_t stage_base, int brow, int bcol,
                                           int kt, int tid) {
    const char* sA = (const char*)g_x1 + ((size_t)brow * BM * INF + kt) * 2;
    const char* sB = (const char*)g_w1 + ((size_t)bcol * BN * INF + kt) * 2;
    // A: 128 rows x 8 chunks of 16B = 1024 chunks
    #pragma unroll
    for (int rep = 0; rep < 2; rep++) {
        int i = rep * NTHREADS + tid;
        int row = i >> 3;
        int ch  = (i & 7) * 16;
        uint32_t so = sw128((uint32_t)(row * 128 + ch));
        CP_ASYNC16(stage_base + so, sA + (size_t)row * (INF * 2) + ch);
    }
    // B: 256 rows x 8 chunks = 2048 chunks
    #pragma unroll
    for (int rep = 0; rep < 4; rep++) {
        int i = rep * NTHREADS + tid;
        int row = i >> 3;
        int ch  = (i & 7) * 16;
        uint32_t so = sw128((uint32_t)(row * 128 + ch));
        CP_ASYNC16(stage_base + A_TILE_BYTES + so, sB + (size_t)row * (INF * 2) + ch);
    }
    CP_COMMIT();
}

// ---------------- fused fp16 GEMM + LSTM epilogue ----------------
__global__ __launch_bounds__(NTHREADS, 1) void lstm_gemm_kernel(
    const float* __restrict__ cx,
    const float* __restrict__ bi, const float* __restrict__ bf_,
    const float* __restrict__ bg, const float* __restrict__ bo,
    float* __restrict__ out)
{
    extern __shared__ char smem[];
    const uint32_t sbase = smem_u32(smem);
    const int tid  = threadIdx.x;
    const int wid  = tid >> 5;
    const int lane = tid & 31;
    const int bcol = blockIdx.x;   // 0..15 over gate-cols (256 wide)
    const int brow = blockIdx.y;   // 0..31 over batch (128 wide)

    const int warpM = wid & 3;     // rows warpM*32
    const int warpN = wid >> 2;    // cols warpN*64

    const uint32_t offA = (uint32_t)((warpM * 32 + (lane & 15)) * 128 + (lane >> 4) * 16);
    const uint32_t sbA  = sw128(offA);
    const uint32_t offB = (uint32_t)((warpN * 64 + (lane & 15)) * 128 + (lane >> 4) * 16);
    const uint32_t sbB  = sw128(offB);

    float acc[2][8][4];   // [mfrag 16-row][nfrag 8-col][4]
    #pragma unroll
    for (int m = 0; m < 2; m++)
        #pragma unroll
        for (int n = 0; n < 8; n++)
            #pragma unroll
            for (int e = 0; e < 4; e++) acc[m][n][e] = 0.f;

    // prologue: NSTAGE-1 stages in flight
    #pragma unroll
    for (int p = 0; p < NSTAGE - 1; p++)
        load_stage(sbase + p * STAGE_BYTES, brow, bcol, p * KC, tid);

    for (int it = 0; it < NKIT; it++) {
        const int slot = it % NSTAGE;
        const uint32_t stg = sbase + slot * STAGE_BYTES;
        const uint32_t tA = stg;
        const uint32_t tB = stg + A_TILE_BYTES;

        // stage `it` ready when all younger issued groups may remain outstanding
        if (it + 2 < NKIT)      CP_WAIT2();
        else if (it + 1 < NKIT) CP_WAIT1();
        else                    CP_WAIT0();
        __syncthreads();

        // issue next load into slot (it+NSTAGE-1)%NSTAGE (consumed in iter it-1)
        if (it + NSTAGE - 1 < NKIT)
            load_stage(sbase + ((it + NSTAGE - 1) % NSTAGE) * STAGE_BYTES,
                       brow, bcol, (it + NSTAGE - 1) * KC, tid);

        #pragma unroll
        for (int kf = 0; kf < 4; kf++) {        // 4 x k16 per stage
            const uint32_t kx = (uint32_t)(kf * 32);
            uint32_t a1[2][4], b1[8][2];
            #pragma unroll
            for (int m = 0; m < 2; m++) {
                uint32_t aoff = (uint32_t)(m * 2048);   // 16 rows * 128B
                LDMX4(a1[m][0], a1[m][1], a1[m][2], a1[m][3], (tA + sbA + aoff) ^ kx);
            }
            #pragma unroll
            for (int g = 0; g < 4; g++) {       // four 16-col groups -> 8 nfrags
                uint32_t boff = (uint32_t)(g * 2048);
                uint32_t r0, r1, r2, r3;
                LDMX4(r0, r1, r2, r3, (tB + sbB + boff) ^ kx);
                b1[g * 2 + 0][0] = r0; b1[g * 2 + 0][1] = r2;
                b1[g * 2 + 1][0] = r1; b1[g * 2 + 1][1] = r3;
            }
            #pragma unroll
            for (int m = 0; m < 2; m++)
                #pragma unroll
                for (int n = 0; n < 8; n++)
                    MMA_F16(acc[m][n], a1[m], b1[n][0], b1[n][1]);
        }
    }

    // ---- dump to smem (fp32 128x256 tile, 128KB <= 192KB) ----
    __syncthreads();
    float* Cs = (float*)smem;
    #pragma unroll
    for (int m = 0; m < 2; m++) {
        const int row = warpM * 32 + m * 16 + (lane >> 2);
        #pragma unroll
        for (int n = 0; n < 8; n++) {
            const int col = warpN * 64 + n * 8 + (lane & 3) * 2;
            *(float2*)&Cs[row * BN + col]       = make_float2(acc[m][n][0], acc[m][n][1]);
            *(float2*)&Cs[(row + 8) * BN + col] = make_float2(acc[m][n][2], acc[m][n][3]);
        }
    }
    __syncthreads();

    // ---- fused LSTM epilogue: cols 4*hl + {i,f,g,o}, hl in [0,64) ----
    #pragma unroll
    for (int r = 0; r < 16; r++) {
        const int idx = r * NTHREADS + tid;     // 0..8191 over (row, hl)
        const int row = idx >> 6;
        const int hl  = idx & 63;
        float4 g4 = *(float4*)&Cs[row * BN + hl * 4];
        const int h = bcol * 64 + hl;
        const int b = brow * BM + row;
        float i_t = g4.x + bi[h];
        float f_t = g4.y + bf_[h];
        float g_t = g4.z + bg[h];
        float o_t = g4.w + bo[h];
        i_t = 1.f / (1.f + expf(-i_t));
        f_t = 1.f / (1.f + expf(-f_t));
        g_t = tanhf(g_t);
        o_t = 1.f / (1.f + expf(-o_t));
        float c_new = f_t * cx[(size_t)b * HID + h] + i_t * g_t;
        float h_new = o_t * tanhf(c_new);
        out[(size_t)b * HID + h] = h_new;
        out[(size_t)BATCH * HID + (size_t)b * HID + h] = c_new;
    }
}

// ---------------- launch ----------------
extern "C" void kernel_launch(void* const* d_in, const int* in_sizes, int n_in,
                              void* d_out, int out_size) {
    const float* input = (const float*)d_in[0];
    const float* hx    = (const float*)d_in[1];
    const float* cx    = (const float*)d_in[2];
    const float* Wi    = (const float*)d_in[3];
    const float* bi    = (const float*)d_in[4];
    const float* Wf    = (const float*)d_in[5];
    const float* bf    = (const float*)d_in[6];
    const float* Wg    = (const float*)d_in[7];
    const float* bg    = (const float*)d_in[8];
    const float* Wo    = (const float*)d_in[9];
    const float* bo    = (const float*)d_in[10];
    float* out = (float*)d_out;

    static bool attr_set = false;
    if (!attr_set) {
        cudaFuncSetAttribute(lstm_gemm_kernel,
                             cudaFuncAttributeMaxDynamicSharedMemorySize, SMEM_TOTAL);
        attr_set = true;
    }

    {
        int units = XUNITS + WUNITS;
        pack_all_kernel<<<(units + 255) / 256, 256>>>(input, hx, Wi, Wf, Wg, Wo);
    }
    {
        dim3 grid(GATES / BN, BATCH / BM);
        lstm_gemm_kernel<<<grid, NTHREADS, SMEM_TOTAL>>>(cx, bi, bf, bg, bo, out);
    }
}

// round 14
// speedup vs baseline: 1.2999x; 1.2999x over previous
#include <cuda_runtime.h>
#include <cuda_fp16.h>
#include <math.h>
#include <stdint.h>

// Problem dims
#define BATCH 4096
#define HID   1024
#define INF   2048           // input + hidden
#define GATES 4096           // 4*HID

// GEMM tiling (fp16 single product) — R12 proven config
#define BM 128
#define BN 128
#define KC 64                // K fp16 elems per stage (128B rows, SW128)
#define NSTAGE 3
#define NKIT (INF / KC)      // 32
#define NTHREADS 512

#define TILE_BYTES  (128 * 128)          // one 128-row x 128B plane (16KB)
#define STAGE_BYTES (2 * TILE_BYTES)     // x1, w1
#define SMEM_TOTAL  (NSTAGE * STAGE_BYTES)   // 98304

static __device__ __forceinline__ uint32_t sw128(uint32_t o) {
    return o ^ ((o >> 3) & 0x70);
}
static __device__ __forceinline__ uint32_t smem_u32(const void* p) {
    uint32_t a;
    asm("{ .reg .u64 t; cvta.to.shared.u64 t, %1; cvt.u32.u64 %0, t; }" : "=r"(a) : "l"(p));
    return a;
}

#define CP_ASYNC16(dst, src) \
    asm volatile("cp.async.cg.shared.global [%0], [%1], 16;" :: "r"(dst), "l"(src))
#define CP_COMMIT() asm volatile("cp.async.commit_group;" ::: "memory")
#define CP_WAIT1()  asm volatile("cp.async.wait_group 1;" ::: "memory")
#define CP_WAIT0()  asm volatile("cp.async.wait_group 0;" ::: "memory")

#define LDMX4(r0, r1, r2, r3, a) \
    asm volatile("ldmatrix.sync.aligned.m8n8.x4.shared.b16 {%0,%1,%2,%3}, [%4];" \
                 : "=r"(r0), "=r"(r1), "=r"(r2), "=r"(r3) : "r"(a))

#define MMA_F16(d, a, b0, b1) \
    asm volatile("mma.sync.aligned.m16n8k16.row.col.f32.f16.f16.f32 " \
                 "{%0,%1,%2,%3}, {%4,%5,%6,%7}, {%8,%9}, {%0,%1,%2,%3};" \
                 : "+f"(d[0]), "+f"(d[1]), "+f"(d[2]), "+f"(d[3]) \
                 : "r"(a[0]), "r"(a[1]), "r"(a[2]), "r"(a[3]), "r"(b0), "r"(b1))

// ---------------- device scratch ----------------
__device__ __half g_x1[(size_t)BATCH * INF];   // fp16(concat(input,hx))
// W packed with row j = (h>>3)*32 + gate*8 + (h&7)  -> in-register gate quads
__device__ __half g_w1[(size_t)GATES * INF];

// ---------------- merged pack kernel (MLP=2: one x-unit + one w-unit) ------
#define XUNITS ((BATCH * INF) / 4)             // 2097152

__global__ void pack_all_kernel(const float* __restrict__ inp,
                                const float* __restrict__ hx,
                                const float* __restrict__ Wi,
                                const float* __restrict__ Wf,
                                const float* __restrict__ Wg,
                                const float* __restrict__ Wo) {
    int idx = blockIdx.x * blockDim.x + threadIdx.x;
    if (idx >= XUNITS) return;
    // ---- x unit ----
    {
        int elem = idx * 4;
        int b = elem >> 11;
        int k = elem & 2047;
        float4 v;
        if (k < HID) v = *(const float4*)(inp + (size_t)b * HID + k);
        else         v = *(const float4*)(hx  + (size_t)b * HID + (k - HID));
        __half q[4];
        q[0] = __float2half_rn(v.x);
        q[1] = __float2half_rn(v.y);
        q[2] = __float2half_rn(v.z);
        q[3] = __float2half_rn(v.w);
        *(uint64_t*)(g_x1 + elem) = *(uint64_t*)q;
    }
    // ---- w unit (independent -> MLP) ----
    {
        long elem = (long)idx * 4;
        int j = (int)(elem >> 11);      // packed dest row
        int k = (int)(elem & 2047);
        int gate = (j >> 3) & 3;
        int h    = ((j >> 5) << 3) + (j & 7);
        const float* W = (gate == 0) ? Wi : (gate == 1) ? Wf : (gate == 2) ? Wg : Wo;
        float4 v = *(const float4*)(W + (long)h * INF + k);
        __half q[4];
        q[0] = __float2half_rn(v.x);
        q[1] = __float2half_rn(v.y);
        q[2] = __float2half_rn(v.z);
        q[3] = __float2half_rn(v.w);
        *(uint64_t*)(g_w1 + elem) = *(uint64_t*)q;
    }
}

// ---------------- stage loader (cp.async, SW128 swizzled) ----------------
__device__ __forceinline__ void load_stage(uint32_t stage_base, int brow, int bcol,
                                           int kt, int tid) {
    const char* s0 = (const char*)g_x1 + ((size_t)brow * 128 * INF + kt) * 2;
    const char* s1 = (const char*)g_w1 + ((size_t)bcol * 128 * INF + kt) * 2;
    const char* gsrc[2] = {s0, s1};
    #pragma unroll
    for (int t = 0; t < 2; t++) {
        uint32_t tile_base = stage_base + t * TILE_BYTES;
        #pragma unroll
        for (int rep = 0; rep < 2; rep++) {
            int i = rep * NTHREADS + tid;      // 0..1023
            int row = i >> 3;
            int ch  = (i & 7) * 16;
            uint32_t so = sw128((uint32_t)(row * 128 + ch));
            CP_ASYNC16(tile_base + so, gsrc[t] + (size_t)row * (INF * 2) + ch);
        }
    }
    CP_COMMIT();
}

// ---------------- fused fp16 GEMM + register-resident LSTM epilogue --------
__global__ __launch_bounds__(NTHREADS, 2) void lstm_gemm_kernel(
    const float* __restrict__ cx,
    const float* __restrict__ bi, const float* __restrict__ bf_,
    const float* __restrict__ bg, const float* __restrict__ bo,
    float* __restrict__ out)
{
    extern __shared__ char smem[];
    const uint32_t sbase = smem_u32(smem);
    const int tid  = threadIdx.x;
    const int wid  = tid >> 5;
    const int lane = tid & 31;
    const int bcol = blockIdx.x;   // 0..31 over gate-col groups (128 packed rows)
    const int brow = blockIdx.y;   // 0..31 over batch (128 wide)

    const int warpM = wid & 3;     // rows warpM*32
    const int warpN = wid >> 2;    // cols warpN*32

    const uint32_t offA = (uint32_t)((warpM * 32 + (lane & 15)) * 128 + (lane >> 4) * 16);
    const uint32_t sbA  = sw128(offA);
    const uint32_t offB = (uint32_t)((warpN * 32 + (lane & 15)) * 128 + (lane >> 4) * 16);
    const uint32_t sbB  = sw128(offB);

    float acc[2][4][4];
    #pragma unroll
    for (int m = 0; m < 2; m++)
        #pragma unroll
        for (int n = 0; n < 4; n++)
            #pragma unroll
            for (int e = 0; e < 4; e++) acc[m][n][e] = 0.f;

    // prologue: NSTAGE-1 = 2 stages in flight
    #pragma unroll
    for (int p = 0; p < NSTAGE - 1; p++)
        load_stage(sbase + p * STAGE_BYTES, brow, bcol, p * KC, tid);

    for (int it = 0; it < NKIT; it++) {
        const int slot = it % NSTAGE;
        const uint32_t stg = sbase + slot * STAGE_BYTES;
        const uint32_t tX1 = stg;
        const uint32_t tW1 = stg + TILE_BYTES;

        if (it < NKIT - 1) CP_WAIT1(); else CP_WAIT0();
        __syncthreads();

        if (it + NSTAGE - 1 < NKIT)
            load_stage(sbase + ((it + NSTAGE - 1) % NSTAGE) * STAGE_BYTES,
                       brow, bcol, (it + NSTAGE - 1) * KC, tid);

        #pragma unroll
        for (int kf = 0; kf < 4; kf++) {        // 4 x k16 per stage
            const uint32_t kx = (uint32_t)(kf * 32);
            uint32_t a1[2][4], b1[4][2];
            #pragma unroll
            for (int m = 0; m < 2; m++) {
                uint32_t aoff = (uint32_t)(m * 2048);   // 16 rows * 128B
                LDMX4(a1[m][0], a1[m][1], a1[m][2], a1[m][3], (tX1 + sbA + aoff) ^ kx);
            }
            #pragma unroll
            for (int g = 0; g < 2; g++) {
                uint32_t boff = (uint32_t)(g * 2048);
                uint32_t r0, r1, r2, r3;
                LDMX4(r0, r1, r2, r3, (tW1 + sbB + boff) ^ kx);
                b1[g * 2 + 0][0] = r0; b1[g * 2 + 0][1] = r2;
                b1[g * 2 + 1][0] = r1; b1[g * 2 + 1][1] = r3;
            }
            #pragma unroll
            for (int m = 0; m < 2; m++)
                #pragma unroll
                for (int n = 0; n < 4; n++)
                    MMA_F16(acc[m][n], a1[m], b1[n][0], b1[n][1]);
        }
    }

    // ---- register-resident LSTM epilogue (no smem, no barrier) ----
    // thread's acc cols map to gates n = {i,f,g,o}, h = hb (e even) / hb+1 (e odd)
    const int hb = bcol * 32 + warpN * 8 + ((lane & 3) << 1);
    const float2 bi2 = *(const float2*)&bi [hb];
    const float2 bf2 = *(const float2*)&bf_[hb];
    const float2 bg2 = *(const float2*)&bg [hb];
    const float2 bo2 = *(const float2*)&bo [hb];

    #pragma unroll
    for (int m = 0; m < 2; m++) {
        #pragma unroll
        for (int half = 0; half < 2; half++) {
            const int e0 = half * 2;
            const int b  = brow * BM + warpM * 32 + m * 16 + (lane >> 2) + half * 8;
            const float2 cx2 = *(const float2*)&cx[(size_t)b * HID + hb];

            float i0 = acc[m][0][e0]     + bi2.x;
            float f0 = acc[m][1][e0]     + bf2.x;
            float g0 = acc[m][2][e0]     + bg2.x;
            float o0 = acc[m][3][e0]     + bo2.x;
            float i1 = acc[m][0][e0 + 1] + bi2.y;
            float f1 = acc[m][1][e0 + 1] + bf2.y;
            float g1 = acc[m][2][e0 + 1] + bg2.y;
            float o1 = acc[m][3][e0 + 1] + bo2.y;

            i0 = 1.f / (1.f + expf(-i0));
            f0 = 1.f / (1.f + expf(-f0));
            g0 = tanhf(g0);
            o0 = 1.f / (1.f + expf(-o0));
            i1 = 1.f / (1.f + expf(-i1));
            f1 = 1.f / (1.f + expf(-f1));
            g1 = tanhf(g1);
            o1 = 1.f / (1.f + expf(-o1));

            float c0 = f0 * cx2.x + i0 * g0;
            float c1 = f1 * cx2.y + i1 * g1;
            float h0 = o0 * tanhf(c0);
            float h1 = o1 * tanhf(c1);

            *(float2*)&out[(size_t)b * HID + hb] = make_float2(h0, h1);
            *(float2*)&out[(size_t)BATCH * HID + (size_t)b * HID + hb] = make_float2(c0, c1);
        }
    }
}

// ---------------- launch ----------------
extern "C" void kernel_launch(void* const* d_in, const int* in_sizes, int n_in,
                              void* d_out, int out_size) {
    const float* input = (const float*)d_in[0];
    const float* hx    = (const float*)d_in[1];
    const float* cx    = (const float*)d_in[2];
    const float* Wi    = (const float*)d_in[3];
    const float* bi    = (const float*)d_in[4];
    const float* Wf    = (const float*)d_in[5];
    const float* bf    = (const float*)d_in[6];
    const float* Wg    = (const float*)d_in[7];
    const float* bg    = (const float*)d_in[8];
    const float* Wo    = (const float*)d_in[9];
    const float* bo    = (const float*)d_in[10];
    float* out = (float*)d_out;

    static bool attr_set = false;
    if (!attr_set) {
        cudaFuncSetAttribute(lstm_gemm_kernel,
                             cudaFuncAttributeMaxDynamicSharedMemorySize, SMEM_TOTAL);
        attr_set = true;
    }

    pack_all_kernel<<<(XUNITS + 255) / 256, 256>>>(input, hx, Wi, Wf, Wg, Wo);
    {
        dim3 grid(GATES / BN, BATCH / BM);
        lstm_gemm_kernel<<<grid, NTHREADS, SMEM_TOTAL>>>(cx, bi, bf, bg, bo, out);
    }
}

// round 15
// speedup vs baseline: 1.3828x; 1.0638x over previous
#include <cuda_runtime.h>
#include <cuda_fp16.h>
#include <math.h>
#include <stdint.h>

// Problem dims
#define BATCH 4096
#define HID   1024
#define INF   2048           // input + hidden
#define GATES 4096           // 4*HID

// GEMM tiling (fp16 single product)
#define BM 128
#define BN 128
#define KC 64                // K fp16 elems per stage (128B rows, SW128)
#define NSTAGE 3
#define NKIT (INF / KC)      // 32
#define NTHREADS 512

#define TILE_BYTES  (128 * 128)          // one 128-row x 128B plane (16KB)
#define STAGE_BYTES (2 * TILE_BYTES)     // x plane + w plane (32KB)
#define MBAR_OFF    (NSTAGE * STAGE_BYTES)
#define SMEM_TOTAL  (MBAR_OFF + 64)      // 98368

static __device__ __forceinline__ uint32_t sw128(uint32_t o) {
    return o ^ ((o >> 3) & 0x70);
}
static __device__ __forceinline__ uint32_t smem_u32(const void* p) {
    uint32_t a;
    asm("{ .reg .u64 t; cvta.to.shared.u64 t, %1; cvt.u32.u64 %0, t; }" : "=r"(a) : "l"(p));
    return a;
}

#define MBAR_INIT(a, n) \
    asm volatile("mbarrier.init.shared.b64 [%0], %1;" :: "r"(a), "r"(n) : "memory")
#define MBAR_EXPECT_TX(a, bytes) \
    asm volatile("mbarrier.arrive.expect_tx.shared.b64 _, [%0], %1;" :: "r"(a), "r"(bytes) : "memory")
#define MBAR_WAIT(a, ph) do { \
    asm volatile("{ .reg .pred P; W%=: mbarrier.try_wait.parity.shared.b64 P, [%0], %1; @P bra D%=; bra W%=; D%=: }" \
                 :: "r"(a), "r"(ph) : "memory"); } while (0)

#define BULK_G2S(dst, src, sz, mbar) \
    asm volatile("cp.async.bulk.shared::cluster.global.mbarrier::complete_tx::bytes [%0], [%1], %2, [%3];" \
                 :: "r"(dst), "l"(src), "r"(sz), "r"(mbar) : "memory")

#define LDMX4(r0, r1, r2, r3, a) \
    asm volatile("ldmatrix.sync.aligned.m8n8.x4.shared.b16 {%0,%1,%2,%3}, [%4];" \
                 : "=r"(r0), "=r"(r1), "=r"(r2), "=r"(r3) : "r"(a))

#define MMA_F16(d, a, b0, b1) \
    asm volatile("mma.sync.aligned.m16n8k16.row.col.f32.f16.f16.f32 " \
                 "{%0,%1,%2,%3}, {%4,%5,%6,%7}, {%8,%9}, {%0,%1,%2,%3};" \
                 : "+f"(d[0]), "+f"(d[1]), "+f"(d[2]), "+f"(d[3]) \
                 : "r"(a[0]), "r"(a[1]), "r"(a[2]), "r"(a[3]), "r"(b0), "r"(b1))

// ---------------- device scratch: PRE-SWIZZLED tiled layout ----------------
// block (t, kc) of 16KB = rows 0..127 x 128B, bytes already in SW128 smem order
__device__ __half g_x1[(size_t)BATCH * INF];
__device__ __half g_w1[(size_t)GATES * INF];   // packed row j = (h>>3)*32 + gate*8 + (h&7)

// ---------------- merged pack kernel (writes swizzled-tiled layout) --------
#define XUNITS ((BATCH * INF) / 4)             // 2097152

__global__ void pack_all_kernel(const float* __restrict__ inp,
                                const float* __restrict__ hx,
                                const float* __restrict__ Wi,
                                const float* __restrict__ Wf,
                                const float* __restrict__ Wg,
                                const float* __restrict__ Wo) {
    int idx = blockIdx.x * blockDim.x + threadIdx.x;
    if (idx >= XUNITS) return;
    // ---- x unit ----
    {
        int elem = idx * 4;
        int b = elem >> 11;
        int k = elem & 2047;
        float4 v;
        if (k < HID) v = *(const float4*)(inp + (size_t)b * HID + k);
        else         v = *(const float4*)(hx  + (size_t)b * HID + (k - HID));
        __half q[4];
        q[0] = __float2half_rn(v.x);
        q[1] = __float2half_rn(v.y);
        q[2] = __float2half_rn(v.z);
        q[3] = __float2half_rn(v.w);
        int trow = b >> 7, row = b & 127, kc = k >> 6, ch = (k & 63) * 2;
        size_t dst = ((size_t)(trow * NKIT + kc) << 14) + sw128((uint32_t)(row * 128 + ch));
        *(uint64_t*)((char*)g_x1 + dst) = *(uint64_t*)q;
    }
    // ---- w unit (independent -> MLP) ----
    {
        long elem = (long)idx * 4;
        int j = (int)(elem >> 11);      // packed dest row
        int k = (int)(elem & 2047);
        int gate = (j >> 3) & 3;
        int h    = ((j >> 5) << 3) + (j & 7);
        const float* W = (gate == 0) ? Wi : (gate == 1) ? Wf : (gate == 2) ? Wg : Wo;
        float4 v = *(const float4*)(W + (long)h * INF + k);
        __half q[4];
        q[0] = __float2half_rn(v.x);
        q[1] = __float2half_rn(v.y);
        q[2] = __float2half_rn(v.z);
        q[3] = __float2half_rn(v.w);
        int trow = j >> 7, row = j & 127, kc = k >> 6, ch = (k & 63) * 2;
        size_t dst = ((size_t)(trow * NKIT + kc) << 14) + sw128((uint32_t)(row * 128 + ch));
        *(uint64_t*)((char*)g_w1 + dst) = *(uint64_t*)q;
    }
}

// ---------------- fused fp16 GEMM + register-resident LSTM epilogue --------
__global__ __launch_bounds__(NTHREADS, 2) void lstm_gemm_kernel(
    const float* __restrict__ cx,
    const float* __restrict__ bi, const float* __restrict__ bf_,
    const float* __restrict__ bg, const float* __restrict__ bo,
    float* __restrict__ out)
{
    extern __shared__ char smem[];
    const uint32_t sbase = smem_u32(smem);
    const int tid  = threadIdx.x;
    const int wid  = tid >> 5;
    const int lane = tid & 31;
    const int bcol = blockIdx.x;   // 0..31 over packed gate-col tiles
    const int brow = blockIdx.y;   // 0..31 over batch tiles

    const char* gA = (const char*)g_x1 + ((size_t)brow * NKIT << 14);
    const char* gB = (const char*)g_w1 + ((size_t)bcol * NKIT << 14);

    const int warpM = wid & 3;     // rows warpM*32
    const int warpN = wid >> 2;    // cols warpN*32

    const uint32_t offA = (uint32_t)((warpM * 32 + (lane & 15)) * 128 + (lane >> 4) * 16);
    const uint32_t sbA  = sw128(offA);
    const uint32_t offB = (uint32_t)((warpN * 32 + (lane & 15)) * 128 + (lane >> 4) * 16);
    const uint32_t sbB  = sw128(offB);

    float acc[2][4][4];
    #pragma unroll
    for (int m = 0; m < 2; m++)
        #pragma unroll
        for (int n = 0; n < 4; n++)
            #pragma unroll
            for (int e = 0; e < 4; e++) acc[m][n][e] = 0.f;

    // init mbarriers + prologue loads (stages 0..NSTAGE-2)
    if (tid == 0) {
        #pragma unroll
        for (int s = 0; s < NSTAGE; s++) MBAR_INIT(sbase + MBAR_OFF + 8 * s, 1);
        asm volatile("fence.proxy.async.shared::cta;" ::: "memory");
    }
    __syncthreads();
    if (tid == 0) {
        #pragma unroll
        for (int p = 0; p < NSTAGE - 1; p++) {
            uint32_t mb = sbase + MBAR_OFF + 8 * p;
            MBAR_EXPECT_TX(mb, 2 * TILE_BYTES);
            BULK_G2S(sbase + p * STAGE_BYTES,              gA + ((size_t)p << 14), TILE_BYTES, mb);
            BULK_G2S(sbase + p * STAGE_BYTES + TILE_BYTES, gB + ((size_t)p << 14), TILE_BYTES, mb);
        }
    }

    for (int it = 0; it < NKIT; it++) {
        const int slot = it % NSTAGE;
        const uint32_t stg = sbase + slot * STAGE_BYTES;
        const uint32_t tX1 = stg;
        const uint32_t tW1 = stg + TILE_BYTES;

        // all warps done with the slot being re-issued (consumed in it-1)
        __syncthreads();
        if (tid == 0 && it + NSTAGE - 1 < NKIT) {
            const int st = it + NSTAGE - 1;
            const int sl = st % NSTAGE;
            uint32_t mb = sbase + MBAR_OFF + 8 * sl;
            MBAR_EXPECT_TX(mb, 2 * TILE_BYTES);
            BULK_G2S(sbase + sl * STAGE_BYTES,              gA + ((size_t)st << 14), TILE_BYTES, mb);
            BULK_G2S(sbase + sl * STAGE_BYTES + TILE_BYTES, gB + ((size_t)st << 14), TILE_BYTES, mb);
        }
        // wait current stage data
        MBAR_WAIT(sbase + MBAR_OFF + 8 * slot, (uint32_t)((it / NSTAGE) & 1));

        #pragma unroll
        for (int kf = 0; kf < 4; kf++) {        // 4 x k16 per stage
            const uint32_t kx = (uint32_t)(kf * 32);
            uint32_t a1[2][4], b1[4][2];
            #pragma unroll
            for (int m = 0; m < 2; m++) {
                uint32_t aoff = (uint32_t)(m * 2048);   // 16 rows * 128B
                LDMX4(a1[m][0], a1[m][1], a1[m][2], a1[m][3], (tX1 + sbA + aoff) ^ kx);
            }
            #pragma unroll
            for (int g = 0; g < 2; g++) {
                uint32_t boff = (uint32_t)(g * 2048);
                uint32_t r0, r1, r2, r3;
                LDMX4(r0, r1, r2, r3, (tW1 + sbB + boff) ^ kx);
                b1[g * 2 + 0][0] = r0; b1[g * 2 + 0][1] = r2;
                b1[g * 2 + 1][0] = r1; b1[g * 2 + 1][1] = r3;
            }
            #pragma unroll
            for (int m = 0; m < 2; m++)
                #pragma unroll
                for (int n = 0; n < 4; n++)
                    MMA_F16(acc[m][n], a1[m], b1[n][0], b1[n][1]);
        }
    }

    // ---- register-resident LSTM epilogue (no smem, no barrier) ----
    const int hb = bcol * 32 + warpN * 8 + ((lane & 3) << 1);
    const float2 bi2 = *(const float2*)&bi [hb];
    const float2 bf2 = *(const float2*)&bf_[hb];
    const float2 bg2 = *(const float2*)&bg [hb];
    const float2 bo2 = *(const float2*)&bo [hb];

    #pragma unroll
    for (int m = 0; m < 2; m++) {
        #pragma unroll
        for (int half = 0; half < 2; half++) {
            const int e0 = half * 2;
            const int b  = brow * BM + warpM * 32 + m * 16 + (lane >> 2) + half * 8;
            const float2 cx2 = *(const float2*)&cx[(size_t)b * HID + hb];

            float i0 = acc[m][0][e0]     + bi2.x;
            float f0 = acc[m][1][e0]     + bf2.x;
            float g0 = acc[m][2][e0]     + bg2.x;
            float o0 = acc[m][3][e0]     + bo2.x;
            float i1 = acc[m][0][e0 + 1] + bi2.y;
            float f1 = acc[m][1][e0 + 1] + bf2.y;
            float g1 = acc[m][2][e0 + 1] + bg2.y;
            float o1 = acc[m][3][e0 + 1] + bo2.y;

            i0 = 1.f / (1.f + expf(-i0));
            f0 = 1.f / (1.f + expf(-f0));
            g0 = tanhf(g0);
            o0 = 1.f / (1.f + expf(-o0));
            i1 = 1.f / (1.f + expf(-i1));
            f1 = 1.f / (1.f + expf(-f1));
            g1 = tanhf(g1);
            o1 = 1.f / (1.f + expf(-o1));

            float c0 = f0 * cx2.x + i0 * g0;
            float c1 = f1 * cx2.y + i1 * g1;
            float h0 = o0 * tanhf(c0);
            float h1 = o1 * tanhf(c1);

            *(float2*)&out[(size_t)b * HID + hb] = make_float2(h0, h1);
            *(float2*)&out[(size_t)BATCH * HID + (size_t)b * HID + hb] = make_float2(c0, c1);
        }
    }
}

// ---------------- launch ----------------
extern "C" void kernel_launch(void* const* d_in, const int* in_sizes, int n_in,
                              void* d_out, int out_size) {
    const float* input = (const float*)d_in[0];
    const float* hx    = (const float*)d_in[1];
    const float* cx    = (const float*)d_in[2];
    const float* Wi    = (const float*)d_in[3];
    const float* bi    = (const float*)d_in[4];
    const float* Wf    = (const float*)d_in[5];
    const float* bf    = (const float*)d_in[6];
    const float* Wg    = (const float*)d_in[7];
    const float* bg    = (const float*)d_in[8];
    const float* Wo    = (const float*)d_in[9];
    const float* bo    = (const float*)d_in[10];
    float* out = (float*)d_out;

    static bool attr_set = false;
    if (!attr_set) {
        cudaFuncSetAttribute(lstm_gemm_kernel,
                             cudaFuncAttributeMaxDynamicSharedMemorySize, SMEM_TOTAL);
        attr_set = true;
    }

    pack_all_kernel<<<(XUNITS + 255) / 256, 256>>>(input, hx, Wi, Wf, Wg, Wo);
    {
        dim3 grid(GATES / BN, BATCH / BM);
        lstm_gemm_kernel<<<grid, NTHREADS, SMEM_TOTAL>>>(cx, bi, bf, bg, bo, out);
    }
}

// round 16
// speedup vs baseline: 1.3954x; 1.0091x over previous
#include <cuda_runtime.h>
#include <cuda_fp16.h>
#include <math.h>
#include <stdint.h>

// Problem dims
#define BATCH 4096
#define HID   1024
#define INF   2048           // input + hidden
#define GATES 4096           // 4*HID

// GEMM tiling (fp16 single product)
#define BM 64
#define BN 128
#define KC 64                // K fp16 elems per stage (128B rows, SW128)
#define NSTAGE 3
#define NKIT (INF / KC)      // 32
#define NTHREADS 256

#define A_PLANE 8192                      // 64 rows x 128B
#define B_PLANE 16384                     // 128 rows x 128B
#define STAGE_BYTES (A_PLANE + B_PLANE)   // 24KB
#define MBAR_OFF    (NSTAGE * STAGE_BYTES)
#define SMEM_TOTAL  (MBAR_OFF + 64)       // 73792

static __device__ __forceinline__ uint32_t sw128(uint32_t o) {
    return o ^ ((o >> 3) & 0x70);
}
static __device__ __forceinline__ uint32_t smem_u32(const void* p) {
    uint32_t a;
    asm("{ .reg .u64 t; cvta.to.shared.u64 t, %1; cvt.u32.u64 %0, t; }" : "=r"(a) : "l"(p));
    return a;
}

#define MBAR_INIT(a, n) \
    asm volatile("mbarrier.init.shared.b64 [%0], %1;" :: "r"(a), "r"(n) : "memory")
#define MBAR_EXPECT_TX(a, bytes) \
    asm volatile("mbarrier.arrive.expect_tx.shared.b64 _, [%0], %1;" :: "r"(a), "r"(bytes) : "memory")
#define MBAR_WAIT(a, ph) do { \
    asm volatile("{ .reg .pred P; W%=: mbarrier.try_wait.parity.shared.b64 P, [%0], %1; @P bra D%=; bra W%=; D%=: }" \
                 :: "r"(a), "r"(ph) : "memory"); } while (0)

#define BULK_G2S(dst, src, sz, mbar) \
    asm volatile("cp.async.bulk.shared::cluster.global.mbarrier::complete_tx::bytes [%0], [%1], %2, [%3];" \
                 :: "r"(dst), "l"(src), "r"(sz), "r"(mbar) : "memory")

#define LDMX4(r0, r1, r2, r3, a) \
    asm volatile("ldmatrix.sync.aligned.m8n8.x4.shared.b16 {%0,%1,%2,%3}, [%4];" \
                 : "=r"(r0), "=r"(r1), "=r"(r2), "=r"(r3) : "r"(a))

#define MMA_F16(d, a, b0, b1) \
    asm volatile("mma.sync.aligned.m16n8k16.row.col.f32.f16.f16.f32 " \
                 "{%0,%1,%2,%3}, {%4,%5,%6,%7}, {%8,%9}, {%0,%1,%2,%3};" \
                 : "+f"(d[0]), "+f"(d[1]), "+f"(d[2]), "+f"(d[3]) \
                 : "r"(a[0]), "r"(a[1]), "r"(a[2]), "r"(a[3]), "r"(b0), "r"(b1))

// ---------------- device scratch: PRE-SWIZZLED tiled layout ----------------
// block (t128, kc) of 16KB = rows 0..127 x 128B, bytes already in SW128 smem order
__device__ __half g_x1[(size_t)BATCH * INF];
__device__ __half g_w1[(size_t)GATES * INF];   // packed row j = (h>>3)*32 + gate*8 + (h&7)

// ---------------- merged pack kernel (writes swizzled-tiled layout) --------
#define XUNITS ((BATCH * INF) / 4)             // 2097152

__global__ void pack_all_kernel(const float* __restrict__ inp,
                                const float* __restrict__ hx,
                                const float* __restrict__ Wi,
                                const float* __restrict__ Wf,
                                const float* __restrict__ Wg,
                                const float* __restrict__ Wo) {
    int idx = blockIdx.x * blockDim.x + threadIdx.x;
    if (idx >= XUNITS) return;
    // ---- x unit ----
    {
        int elem = idx * 4;
        int b = elem >> 11;
        int k = elem & 2047;
        float4 v;
        if (k < HID) v = *(const float4*)(inp + (size_t)b * HID + k);
        else         v = *(const float4*)(hx  + (size_t)b * HID + (k - HID));
        __half q[4];
        q[0] = __float2half_rn(v.x);
        q[1] = __float2half_rn(v.y);
        q[2] = __float2half_rn(v.z);
        q[3] = __float2half_rn(v.w);
        int trow = b >> 7, row = b & 127, kc = k >> 6, ch = (k & 63) * 2;
        size_t dst = ((size_t)(trow * NKIT + kc) << 14) + sw128((uint32_t)(row * 128 + ch));
        *(uint64_t*)((char*)g_x1 + dst) = *(uint64_t*)q;
    }
    // ---- w unit (independent -> MLP) ----
    {
        long elem = (long)idx * 4;
        int j = (int)(elem >> 11);      // packed dest row
        int k = (int)(elem & 2047);
        int gate = (j >> 3) & 3;
        int h    = ((j >> 5) << 3) + (j & 7);
        const float* W = (gate == 0) ? Wi : (gate == 1) ? Wf : (gate == 2) ? Wg : Wo;
        float4 v = *(const float4*)(W + (long)h * INF + k);
        __half q[4];
        q[0] = __float2half_rn(v.x);
        q[1] = __float2half_rn(v.y);
        q[2] = __float2half_rn(v.z);
        q[3] = __float2half_rn(v.w);
        int trow = j >> 7, row = j & 127, kc = k >> 6, ch = (k & 63) * 2;
        size_t dst = ((size_t)(trow * NKIT + kc) << 14) + sw128((uint32_t)(row * 128 + ch));
        *(uint64_t*)((char*)g_w1 + dst) = *(uint64_t*)q;
    }
}

// ---------------- fused fp16 GEMM + register-resident LSTM epilogue --------
__global__ __launch_bounds__(NTHREADS, 3) void lstm_gemm_kernel(
    const float* __restrict__ cx,
    const float* __restrict__ bi, const float* __restrict__ bf_,
    const float* __restrict__ bg, const float* __restrict__ bo,
    float* __restrict__ out)
{
    extern __shared__ char smem[];
    const uint32_t sbase = smem_u32(smem);
    const int tid  = threadIdx.x;
    const int wid  = tid >> 5;
    const int lane = tid & 31;
    const int bcol = blockIdx.x;   // 0..31 over packed gate-col tiles (128 rows)
    const int brow = blockIdx.y;   // 0..63 over batch tiles (64 rows)

    // A: 64-row slice = contiguous 8KB half of a 16KB 128-row block
    const char* gA = (const char*)g_x1 + ((size_t)((brow >> 1) * NKIT) << 14)
                   + (size_t)(brow & 1) * A_PLANE;
    const char* gB = (const char*)g_w1 + ((size_t)(bcol * NKIT) << 14);

    const int warpM = wid & 1;     // rows warpM*32
    const int warpN = wid >> 1;    // cols warpN*32

    const uint32_t offA = (uint32_t)((warpM * 32 + (lane & 15)) * 128 + (lane >> 4) * 16);
    const uint32_t sbA  = sw128(offA);
    const uint32_t offB = (uint32_t)((warpN * 32 + (lane & 15)) * 128 + (lane >> 4) * 16);
    const uint32_t sbB  = sw128(offB);

    float acc[2][4][4];
    #pragma unroll
    for (int m = 0; m < 2; m++)
        #pragma unroll
        for (int n = 0; n < 4; n++)
            #pragma unroll
            for (int e = 0; e < 4; e++) acc[m][n][e] = 0.f;

    // init mbarriers + prologue loads (stages 0..NSTAGE-2)
    if (tid == 0) {
        #pragma unroll
        for (int s = 0; s < NSTAGE; s++) MBAR_INIT(sbase + MBAR_OFF + 8 * s, 1);
        asm volatile("fence.proxy.async.shared::cta;" ::: "memory");
    }
    __syncthreads();
    if (tid == 0) {
        #pragma unroll
        for (int p = 0; p < NSTAGE - 1; p++) {
            uint32_t mb = sbase + MBAR_OFF + 8 * p;
            MBAR_EXPECT_TX(mb, STAGE_BYTES);
            BULK_G2S(sbase + p * STAGE_BYTES,           gA + ((size_t)p << 14), A_PLANE, mb);
            BULK_G2S(sbase + p * STAGE_BYTES + A_PLANE, gB + ((size_t)p << 14), B_PLANE, mb);
        }
    }

    for (int it = 0; it < NKIT; it++) {
        const int slot = it % NSTAGE;
        const uint32_t stg = sbase + slot * STAGE_BYTES;
        const uint32_t tX1 = stg;
        const uint32_t tW1 = stg + A_PLANE;

        // all warps done with the slot being re-issued (consumed in it-1)
        __syncthreads();
        if (tid == 0 && it + NSTAGE - 1 < NKIT) {
            const int st = it + NSTAGE - 1;
            const int sl = st % NSTAGE;
            uint32_t mb = sbase + MBAR_OFF + 8 * sl;
            MBAR_EXPECT_TX(mb, STAGE_BYTES);
            BULK_G2S(sbase + sl * STAGE_BYTES,           gA + ((size_t)st << 14), A_PLANE, mb);
            BULK_G2S(sbase + sl * STAGE_BYTES + A_PLANE, gB + ((size_t)st << 14), B_PLANE, mb);
        }
        // wait current stage data
        MBAR_WAIT(sbase + MBAR_OFF + 8 * slot, (uint32_t)((it / NSTAGE) & 1));

        #pragma unroll
        for (int kf = 0; kf < 4; kf++) {        // 4 x k16 per stage
            const uint32_t kx = (uint32_t)(kf * 32);
            uint32_t a1[2][4], b1[4][2];
            #pragma unroll
            for (int m = 0; m < 2; m++) {
                uint32_t aoff = (uint32_t)(m * 2048);   // 16 rows * 128B
                LDMX4(a1[m][0], a1[m][1], a1[m][2], a1[m][3], (tX1 + sbA + aoff) ^ kx);
            }
            #pragma unroll
            for (int g = 0; g < 2; g++) {
                uint32_t boff = (uint32_t)(g * 2048);
                uint32_t r0, r1, r2, r3;
                LDMX4(r0, r1, r2, r3, (tW1 + sbB + boff) ^ kx);
                b1[g * 2 + 0][0] = r0; b1[g * 2 + 0][1] = r2;
                b1[g * 2 + 1][0] = r1; b1[g * 2 + 1][1] = r3;
            }
            #pragma unroll
            for (int m = 0; m < 2; m++)
                #pragma unroll
                for (int n = 0; n < 4; n++)
                    MMA_F16(acc[m][n], a1[m], b1[n][0], b1[n][1]);
        }
    }

    // ---- register-resident LSTM epilogue (no smem, no barrier) ----
    const int hb = bcol * 32 + warpN * 8 + ((lane & 3) << 1);
    const float2 bi2 = *(const float2*)&bi [hb];
    const float2 bf2 = *(const float2*)&bf_[hb];
    const float2 bg2 = *(const float2*)&bg [hb];
    const float2 bo2 = *(const float2*)&bo [hb];

    #pragma unroll
    for (int m = 0; m < 2; m++) {
        #pragma unroll
        for (int half = 0; half < 2; half++) {
            const int e0 = half * 2;
            const int b  = brow * BM + warpM * 32 + m * 16 + (lane >> 2) + half * 8;
            const float2 cx2 = *(const float2*)&cx[(size_t)b * HID + hb];

            float i0 = acc[m][0][e0]     + bi2.x;
            float f0 = acc[m][1][e0]     + bf2.x;
            float g0 = acc[m][2][e0]     + bg2.x;
            float o0 = acc[m][3][e0]     + bo2.x;
            float i1 = acc[m][0][e0 + 1] + bi2.y;
            float f1 = acc[m][1][e0 + 1] + bf2.y;
            float g1 = acc[m][2][e0 + 1] + bg2.y;
            float o1 = acc[m][3][e0 + 1] + bo2.y;

            i0 = 1.f / (1.f + expf(-i0));
            f0 = 1.f / (1.f + expf(-f0));
            g0 = tanhf(g0);
            o0 = 1.f / (1.f + expf(-o0));
            i1 = 1.f / (1.f + expf(-i1));
            f1 = 1.f / (1.f + expf(-f1));
            g1 = tanhf(g1);
            o1 = 1.f / (1.f + expf(-o1));

            float c0 = f0 * cx2.x + i0 * g0;
            float c1 = f1 * cx2.y + i1 * g1;
            float h0 = o0 * tanhf(c0);
            float h1 = o1 * tanhf(c1);

            *(float2*)&out[(size_t)b * HID + hb] = make_float2(h0, h1);
            *(float2*)&out[(size_t)BATCH * HID + (size_t)b * HID + hb] = make_float2(c0, c1);
        }
    }
}

// ---------------- launch ----------------
extern "C" void kernel_launch(void* const* d_in, const int* in_sizes, int n_in,
                              void* d_out, int out_size) {
    const float* input = (const float*)d_in[0];
    const float* hx    = (const float*)d_in[1];
    const float* cx    = (const float*)d_in[2];
    const float* Wi    = (const float*)d_in[3];
    const float* bi    = (const float*)d_in[4];
    const float* Wf    = (const float*)d_in[5];
    const float* bf    = (const float*)d_in[6];
    const float* Wg    = (const float*)d_in[7];
    const float* bg    = (const float*)d_in[8];
    const float* Wo    = (const float*)d_in[9];
    const float* bo    = (const float*)d_in[10];
    float* out = (float*)d_out;

    static bool attr_set = false;
    if (!attr_set) {
        cudaFuncSetAttribute(lstm_gemm_kernel,
                             cudaFuncAttributeMaxDynamicSharedMemorySize, SMEM_TOTAL);
        attr_set = true;
    }

    pack_all_kernel<<<(XUNITS + 255) / 256, 256>>>(input, hx, Wi, Wf, Wg, Wo);
    {
        dim3 grid(GATES / BN, BATCH / BM);
        lstm_gemm_kernel<<<grid, NTHREADS, SMEM_TOTAL>>>(cx, bi, bf, bg, bo, out);
    }
}